// round 15
// baseline (speedup 1.0000x reference)
#include <cuda_runtime.h>
#include <cuda_fp16.h>
#include <cstdint>
#include <cstddef>

// ============================================================================
// Mex forward, fused: y[n,i] = log( sum_k exp(P[n,k]) * exp(O[i,k]) ) - ln(576)
// K permuted: k' = f*64 + c (f = fh*3+fw), both operands.
// R13 structure (CTA 64M x 128N, 8 warps 32x32, slab pitch 72 + XOR swizzle,
// direct-ldmatrix A, 4-deep B ring, 2 CTA/SM) with the MMA switched to
// f16-ACCUMULATE (2x HMMA rate) + per-chunk promotion to fp32 registers.
// Precision: per-chunk f16 rounding ~4.8e-4 on chunk partials -> ~3.5e-4 in y.
// ============================================================================

#define DINL __device__ __forceinline__

static constexpr int NI   = 256;
static constexpr int KTOT = 576;
static constexpr int NCHUNK = 9;
static constexpr float LOG_K = 6.3561076606958915f;  // ln(576)

static constexpr int SLAB_P  = 72;                     // halves per (ihl,iw') row
static constexpr int ROW_B   = SLAB_P * 2;             // 144 bytes (9 x 16)
static constexpr int B_OFF   = 46848;                  // 5*65*144=46800, 128-al
static constexpr int B_STAGE = 128 * 128;              // 16 KB
static constexpr int NSTG    = 4;
static constexpr int SMEM_BYTES = B_OFF + NSTG * B_STAGE;  // 112384 -> 2 CTA/SM

__device__ __half g_B[(size_t)NI * KTOT];              // exp(offsets), permuted K

// ---------------------------------------------------------------------------
DINL uint32_t smem_u32(const void* p) {
    uint32_t a;
    asm("{ .reg .u64 t; cvta.to.shared.u64 t, %1; cvt.u32.u64 %0, t; }"
        : "=r"(a) : "l"(p));
    return a;
}
DINL void cp_async16(uint32_t smem_addr, const void* gptr) {
    asm volatile("cp.async.cg.shared.global [%0], [%1], 16;"
                 :: "r"(smem_addr), "l"(gptr) : "memory");
}
DINL void cp_commit() { asm volatile("cp.async.commit_group;" ::: "memory"); }
template <int N> DINL void cp_wait() {
    asm volatile("cp.async.wait_group %0;" :: "n"(N) : "memory");
}
DINL void ldm_x4(uint32_t addr, uint32_t& r0, uint32_t& r1,
                 uint32_t& r2, uint32_t& r3) {
    asm volatile("ldmatrix.sync.aligned.m8n8.x4.shared.b16 {%0,%1,%2,%3}, [%4];"
                 : "=r"(r0), "=r"(r1), "=r"(r2), "=r"(r3) : "r"(addr));
}
// f16-accumulate MMA: D(2 regs of half2) = A*B + D, 2x rate vs f32 acc
DINL void mma16816_h(uint32_t* d, const uint32_t* a, uint32_t b0, uint32_t b1) {
    asm volatile(
        "mma.sync.aligned.m16n8k16.row.col.f16.f16.f16.f16 "
        "{%0,%1}, {%2,%3,%4,%5}, {%6,%7}, {%0,%1};"
        : "+r"(d[0]), "+r"(d[1])
        : "r"(a[0]), "r"(a[1]), "r"(a[2]), "r"(a[3]), "r"(b0), "r"(b1));
}
DINL uint32_t sw128(uint32_t off) { return off ^ ((off >> 3) & 0x70); }

// ---------------------------------------------------------------------------
// pass0: B'[i, f*64+c] = fp16(exp(offsets[i, c*9+f]))
// ---------------------------------------------------------------------------
__global__ void mex_pass0(const float* __restrict__ offs, __half* __restrict__ Bm) {
    int j = blockIdx.x * blockDim.x + threadIdx.x;
    if (j < NI * KTOT) {
        int i = j / KTOT;
        int r = j - i * KTOT;
        int f = r >> 6;
        int c = r & 63;
        Bm[j] = __float2half_rn(__expf(offs[i * KTOT + c * 9 + f]));
    }
}

// ---------------------------------------------------------------------------
// fused kernel.  grid = (2, 1024): x = N-split (n0 = 0/128), y = b*16 + p.
// 256 threads, 8 warps: wm = wid&1 (M 32-band = ohl), wn = wid>>1 (N 32-band).
// Slab xs[ihl 0..4][iw' 0..64][c], pitch 72 halves, c byte-offset XOR-swizzled
// by ((iw'>>1)&7)<<4.
// ---------------------------------------------------------------------------
__global__ void __launch_bounds__(256, 2) mex_fused(const float* __restrict__ x,
                                                    const __half* __restrict__ Bg,
                                                    float* __restrict__ out) {
    extern __shared__ __align__(128) char sm[];
    const uint32_t sb = smem_u32(sm);

    const int tid = threadIdx.x;
    const int l   = tid & 31;
    const int wid = tid >> 5;

    const int n0 = blockIdx.x << 7;          // 0 or 128
    const int bo = blockIdx.y;
    const int b  = bo >> 4;
    const int p  = bo & 15;                  // oh pair: oh = 2p, 2p+1
    const float* xb = x + ((size_t)b << 18);

    auto load_B = [&](int stage, int kc) {
        const uint32_t b_s = sb + B_OFF + stage * B_STAGE;
        const __half* bp = Bg + (size_t)n0 * KTOT + kc * 64;
#pragma unroll
        for (int i = 0; i < 4; i++) {
            int idx = tid + i * 256;         // 0..1023
            int row = idx >> 3, ch = idx & 7;
            uint32_t off = (uint32_t)(row * 128 + ch * 16);
            cp_async16(b_s + sw128(off), bp + (size_t)row * KTOT + ch * 8);
        }
        cp_commit();
    };
    load_B(0, 0);
    load_B(1, 1);
    load_B(2, 2);

    // ---- slab fill: warp wid owns c-octet c0 = wid*8; register transpose ----
    {
        const int c0 = wid << 3;             // 0..56
        const uint32_t cb = (uint32_t)(c0 << 1);
#pragma unroll
        for (int ihl = 0; ihl < 5; ihl++) {
            const int ih = 4 * p - 1 + ihl;          // -1..63
#pragma unroll
            for (int h = 0; h < 2; h++) {
                const int w = (h << 5) + l;          // 0..63 ; iw' = w+1
                __align__(16) __half tmp[8];
                if (ih >= 0) {
                    const float* ptr = xb + ((size_t)c0 << 12) + (ih << 6) + w;
#pragma unroll
                    for (int j = 0; j < 8; j++)
                        tmp[j] = __float2half_rn(__expf(ptr[(size_t)j << 12]));
                } else {
#pragma unroll
                    for (int j = 0; j < 8; j++) tmp[j] = __ushort_as_half(0x3C00);
                }
                uint32_t pat = (uint32_t)((((w + 1) >> 1) & 7) << 4);
                uint32_t off = (uint32_t)((ihl * 65 + w + 1) * ROW_B) + (cb ^ pat);
                *reinterpret_cast<uint4*>(sm + off) =
                    *reinterpret_cast<const uint4*>(tmp);
            }
        }
        // left pad iw'=0 (pat = 0): 5 rows x 32 half2 = 160 slots
        if (tid < 160) {
            int ihl = tid >> 5;
            int c2  = (tid & 31) << 1;
            *reinterpret_cast<__half2*>(sm + ihl * 65 * ROW_B + (c2 << 1)) =
                __halves2half2(__ushort_as_half(0x3C00), __ushort_as_half(0x3C00));
        }
    }
    __syncthreads();                         // slab complete

    const int wm = wid & 1;                  // M band wm*32 (= ohl)
    const int wn = wid >> 1;                 // N band wn*32
    float facc[2][4][4];
#pragma unroll
    for (int a = 0; a < 2; a++)
#pragma unroll
        for (int n = 0; n < 4; n++)
#pragma unroll
            for (int e = 0; e < 4; e++) facc[a][n][e] = 0.0f;

    const uint32_t lrow = (uint32_t)(l & 15);
    const uint32_t lcol = (uint32_t)((l >> 4) * 16);
    const int ow_lane = (((l >> 3) & 1) << 3) + (l & 7);
    const uint32_t kh16 = (uint32_t)(((l >> 4) & 1) << 4);

    // ---- mainloop: 4-deep ring ----
    for (int kc = 0; kc < NCHUNK; kc++) {
        if (kc < NCHUNK - 3) { load_B((kc + 3) & 3, kc + 3); cp_wait<3>(); }
        else if (kc == NCHUNK - 3) { cp_wait<2>(); }
        else if (kc == NCHUNK - 2) { cp_wait<1>(); }
        else                       { cp_wait<0>(); }
        __syncthreads();                     // B(kc) visible

        const int fh = (kc * 11) >> 5;       // kc/3
        const int fw = kc - 3 * fh;
        const int fwd = fw >> 1;
        uint32_t abase[2], apat[2];
#pragma unroll
        for (int mt = 0; mt < 2; mt++) {
            int ow = mt * 16 + ow_lane;      // 0..31
            abase[mt] = sb + (uint32_t)(((2 * wm + fh) * 65 + 2 * ow + fw) * ROW_B);
            apat[mt]  = (uint32_t)(((ow + fwd) & 7) << 4);
        }
        const uint32_t b_s = sb + B_OFF + (uint32_t)((kc & 3) * B_STAGE);

        uint32_t hacc[2][4][2];              // f16 chunk-partial accumulators
#pragma unroll
        for (int mt = 0; mt < 2; mt++)
#pragma unroll
            for (int nt = 0; nt < 4; nt++) { hacc[mt][nt][0] = 0u; hacc[mt][nt][1] = 0u; }

#pragma unroll
        for (int ks = 0; ks < 4; ks++) {
            uint32_t af[2][4], bf[2][4];
#pragma unroll
            for (int mt = 0; mt < 2; mt++) {
                uint32_t koff = ((uint32_t)(ks * 32) + kh16) ^ apat[mt];
                ldm_x4(abase[mt] + koff, af[mt][0], af[mt][1], af[mt][2], af[mt][3]);
            }
#pragma unroll
            for (int bt = 0; bt < 2; bt++) {
                uint32_t off = (uint32_t)((wn * 32 + bt * 16 + lrow) * 128 +
                                          ks * 32 + lcol);
                ldm_x4(b_s + sw128(off), bf[bt][0], bf[bt][1], bf[bt][2], bf[bt][3]);
            }
#pragma unroll
            for (int mt = 0; mt < 2; mt++)
#pragma unroll
                for (int nt = 0; nt < 4; nt++)
                    mma16816_h(hacc[mt][nt], af[mt],
                               bf[nt >> 1][nt & 1], bf[nt >> 1][(nt & 1) + 2]);
        }

        // promote chunk partials to fp32 (fma pipe is idle)
#pragma unroll
        for (int mt = 0; mt < 2; mt++)
#pragma unroll
            for (int nt = 0; nt < 4; nt++) {
                __half2 h0 = *reinterpret_cast<__half2*>(&hacc[mt][nt][0]);
                __half2 h1 = *reinterpret_cast<__half2*>(&hacc[mt][nt][1]);
                facc[mt][nt][0] += __low2float(h0);
                facc[mt][nt][1] += __high2float(h0);
                facc[mt][nt][2] += __low2float(h1);
                facc[mt][nt][3] += __high2float(h1);
            }
    }

    // ---- epilogue: 4 groups of 32 instances; transpose in smem (reuse slab) ----
    float* fs = reinterpret_cast<float*>(sm);        // [64][33] floats = 8448 B
#pragma unroll 1
    for (int g = 0; g < 4; g++) {
        __syncthreads();
        if (wn == g) {
#pragma unroll
            for (int mt = 0; mt < 2; mt++)
#pragma unroll
                for (int nt = 0; nt < 4; nt++)
#pragma unroll
                    for (int e = 0; e < 4; e++) {
                        int row = (l >> 2) + ((e >> 1) << 3);
                        int col = ((l & 3) << 1) + (e & 1);
                        int ml  = wm * 32 + mt * 16 + row;   // 0..63
                        int nl  = (nt << 3) + col;           // 0..31
                        fs[ml * 33 + nl] = __logf(facc[mt][nt][e]) - LOG_K;
                    }
        }
        __syncthreads();
        const int i_loc = tid >> 3;                  // 0..31
        const int mc    = (tid & 7) << 3;            // 0..56
        float* ob = out + ((size_t)b << 18)
                        + (((size_t)(n0 + g * 32 + i_loc)) << 10) + p * 64 + mc;
#pragma unroll
        for (int j = 0; j < 2; j++) {
            float4 v;
            v.x = fs[(mc + j * 4 + 0) * 33 + i_loc];
            v.y = fs[(mc + j * 4 + 1) * 33 + i_loc];
            v.z = fs[(mc + j * 4 + 2) * 33 + i_loc];
            v.w = fs[(mc + j * 4 + 3) * 33 + i_loc];
            *reinterpret_cast<float4*>(ob + j * 4) = v;
        }
    }
}

// ---------------------------------------------------------------------------
extern "C" void kernel_launch(void* const* d_in, const int* in_sizes, int n_in,
                              void* d_out, int out_size) {
    const float* x    = (const float*)d_in[0];
    const float* offs = (const float*)d_in[1];
    if (n_in >= 2 && in_sizes[0] == NI * KTOT) {  // defensive: swap if order flipped
        const float* t = x; x = offs; offs = t;
    }
    float* out = (float*)d_out;

    __half* Bp = nullptr;
    cudaGetSymbolAddress((void**)&Bp, g_B);
    cudaFuncSetAttribute(mex_fused, cudaFuncAttributeMaxDynamicSharedMemorySize,
                         SMEM_BYTES);

    mex_pass0<<<(NI * KTOT + 255) / 256, 256>>>(offs, Bp);
    dim3 grid(2, 64 * 16);
    mex_fused<<<grid, 256, SMEM_BYTES>>>(x, Bp, out);
}

// round 16
// speedup vs baseline: 1.1037x; 1.1037x over previous
#include <cuda_runtime.h>
#include <cuda_fp16.h>
#include <cstdint>
#include <cstddef>

// ============================================================================
// Mex forward, fused: y[n,i] = log( sum_k exp(P[n,k]) * exp(O[i,k]) ) - ln(576)
// K permuted: k' = f*64 + c (f = fh*3+fw), both operands.
// R13 base (CTA 64M x 128N, 8 warps 32x32, slab pitch 72 + XOR swizzle,
// direct-ldmatrix A, 4-deep B ring, 2 CTA/SM, f32 acc) + SOFTWARE-PIPELINED
// fragments: LDSM for ks+1 issues before the MMAs of ks (hides ~30cyc LDSM
// latency under 16 MMA issues) -- attacks the measured LDSM->MMA stall.
// ============================================================================

#define DINL __device__ __forceinline__

static constexpr int NI   = 256;
static constexpr int KTOT = 576;
static constexpr int NCHUNK = 9;
static constexpr float LOG_K = 6.3561076606958915f;  // ln(576)

static constexpr int SLAB_P  = 72;                     // halves per (ihl,iw') row
static constexpr int ROW_B   = SLAB_P * 2;             // 144 bytes (9 x 16)
static constexpr int B_OFF   = 46848;                  // 5*65*144=46800, 128-al
static constexpr int B_STAGE = 128 * 128;              // 16 KB
static constexpr int NSTG    = 4;
static constexpr int SMEM_BYTES = B_OFF + NSTG * B_STAGE;  // 112384 -> 2 CTA/SM

__device__ __half g_B[(size_t)NI * KTOT];              // exp(offsets), permuted K

// ---------------------------------------------------------------------------
DINL uint32_t smem_u32(const void* p) {
    uint32_t a;
    asm("{ .reg .u64 t; cvta.to.shared.u64 t, %1; cvt.u32.u64 %0, t; }"
        : "=r"(a) : "l"(p));
    return a;
}
DINL void cp_async16(uint32_t smem_addr, const void* gptr) {
    asm volatile("cp.async.cg.shared.global [%0], [%1], 16;"
                 :: "r"(smem_addr), "l"(gptr) : "memory");
}
DINL void cp_commit() { asm volatile("cp.async.commit_group;" ::: "memory"); }
template <int N> DINL void cp_wait() {
    asm volatile("cp.async.wait_group %0;" :: "n"(N) : "memory");
}
DINL void ldm_x4(uint32_t addr, uint32_t& r0, uint32_t& r1,
                 uint32_t& r2, uint32_t& r3) {
    asm volatile("ldmatrix.sync.aligned.m8n8.x4.shared.b16 {%0,%1,%2,%3}, [%4];"
                 : "=r"(r0), "=r"(r1), "=r"(r2), "=r"(r3) : "r"(addr));
}
DINL void mma16816(float* c, const uint32_t* a, uint32_t b0, uint32_t b1) {
    asm volatile(
        "mma.sync.aligned.m16n8k16.row.col.f32.f16.f16.f32 "
        "{%0,%1,%2,%3}, {%4,%5,%6,%7}, {%8,%9}, {%0,%1,%2,%3};"
        : "+f"(c[0]), "+f"(c[1]), "+f"(c[2]), "+f"(c[3])
        : "r"(a[0]), "r"(a[1]), "r"(a[2]), "r"(a[3]), "r"(b0), "r"(b1));
}
DINL uint32_t sw128(uint32_t off) { return off ^ ((off >> 3) & 0x70); }

// ---------------------------------------------------------------------------
// pass0: B'[i, f*64+c] = fp16(exp(offsets[i, c*9+f]))
// ---------------------------------------------------------------------------
__global__ void mex_pass0(const float* __restrict__ offs, __half* __restrict__ Bm) {
    int j = blockIdx.x * blockDim.x + threadIdx.x;
    if (j < NI * KTOT) {
        int i = j / KTOT;
        int r = j - i * KTOT;
        int f = r >> 6;
        int c = r & 63;
        Bm[j] = __float2half_rn(__expf(offs[i * KTOT + c * 9 + f]));
    }
}

// ---------------------------------------------------------------------------
// fused kernel.  grid = (2, 1024): x = N-split (n0 = 0/128), y = b*16 + p.
// 256 threads, 8 warps: wm = wid&1 (M 32-band = ohl), wn = wid>>1 (N 32-band).
// Slab xs[ihl 0..4][iw' 0..64][c], pitch 72 halves, c byte-offset XOR-swizzled
// by ((iw'>>1)&7)<<4.
// ---------------------------------------------------------------------------
__global__ void __launch_bounds__(256, 2) mex_fused(const float* __restrict__ x,
                                                    const __half* __restrict__ Bg,
                                                    float* __restrict__ out) {
    extern __shared__ __align__(128) char sm[];
    const uint32_t sb = smem_u32(sm);

    const int tid = threadIdx.x;
    const int l   = tid & 31;
    const int wid = tid >> 5;

    const int n0 = blockIdx.x << 7;          // 0 or 128
    const int bo = blockIdx.y;
    const int b  = bo >> 4;
    const int p  = bo & 15;                  // oh pair: oh = 2p, 2p+1
    const float* xb = x + ((size_t)b << 18);

    auto load_B = [&](int stage, int kc) {
        const uint32_t b_s = sb + B_OFF + stage * B_STAGE;
        const __half* bp = Bg + (size_t)n0 * KTOT + kc * 64;
#pragma unroll
        for (int i = 0; i < 4; i++) {
            int idx = tid + i * 256;         // 0..1023
            int row = idx >> 3, ch = idx & 7;
            uint32_t off = (uint32_t)(row * 128 + ch * 16);
            cp_async16(b_s + sw128(off), bp + (size_t)row * KTOT + ch * 8);
        }
        cp_commit();
    };
    load_B(0, 0);
    load_B(1, 1);
    load_B(2, 2);

    // ---- slab fill: warp wid owns c-octet c0 = wid*8; register transpose ----
    {
        const int c0 = wid << 3;             // 0..56
        const uint32_t cb = (uint32_t)(c0 << 1);
#pragma unroll
        for (int ihl = 0; ihl < 5; ihl++) {
            const int ih = 4 * p - 1 + ihl;          // -1..63
#pragma unroll
            for (int h = 0; h < 2; h++) {
                const int w = (h << 5) + l;          // 0..63 ; iw' = w+1
                __align__(16) __half tmp[8];
                if (ih >= 0) {
                    const float* ptr = xb + ((size_t)c0 << 12) + (ih << 6) + w;
#pragma unroll
                    for (int j = 0; j < 8; j++)
                        tmp[j] = __float2half_rn(__expf(ptr[(size_t)j << 12]));
                } else {
#pragma unroll
                    for (int j = 0; j < 8; j++) tmp[j] = __ushort_as_half(0x3C00);
                }
                uint32_t pat = (uint32_t)((((w + 1) >> 1) & 7) << 4);
                uint32_t off = (uint32_t)((ihl * 65 + w + 1) * ROW_B) + (cb ^ pat);
                *reinterpret_cast<uint4*>(sm + off) =
                    *reinterpret_cast<const uint4*>(tmp);
            }
        }
        // left pad iw'=0 (pat = 0): 5 rows x 32 half2 = 160 slots
        if (tid < 160) {
            int ihl = tid >> 5;
            int c2  = (tid & 31) << 1;
            *reinterpret_cast<__half2*>(sm + ihl * 65 * ROW_B + (c2 << 1)) =
                __halves2half2(__ushort_as_half(0x3C00), __ushort_as_half(0x3C00));
        }
    }
    __syncthreads();                         // slab complete

    const int wm = wid & 1;                  // M band wm*32 (= ohl)
    const int wn = wid >> 1;                 // N band wn*32
    float acc[2][4][4];
#pragma unroll
    for (int a = 0; a < 2; a++)
#pragma unroll
        for (int n = 0; n < 4; n++)
#pragma unroll
            for (int e = 0; e < 4; e++) acc[a][n][e] = 0.0f;

    const uint32_t lrow = (uint32_t)(l & 15);
    const uint32_t lcol = (uint32_t)((l >> 4) * 16);
    const int ow_lane = (((l >> 3) & 1) << 3) + (l & 7);
    const uint32_t kh16 = (uint32_t)(((l >> 4) & 1) << 4);

    // ---- mainloop: 4-deep B ring, ks-pipelined fragments ----
    for (int kc = 0; kc < NCHUNK; kc++) {
        if (kc < NCHUNK - 3) { load_B((kc + 3) & 3, kc + 3); cp_wait<3>(); }
        else if (kc == NCHUNK - 3) { cp_wait<2>(); }
        else if (kc == NCHUNK - 2) { cp_wait<1>(); }
        else                       { cp_wait<0>(); }
        __syncthreads();                     // B(kc) visible

        const int fh = (kc * 11) >> 5;       // kc/3
        const int fw = kc - 3 * fh;
        const int fwd = fw >> 1;
        uint32_t abase[2], apat[2];
#pragma unroll
        for (int mt = 0; mt < 2; mt++) {
            int ow = mt * 16 + ow_lane;      // 0..31
            abase[mt] = sb + (uint32_t)(((2 * wm + fh) * 65 + 2 * ow + fw) * ROW_B);
            apat[mt]  = (uint32_t)(((ow + fwd) & 7) << 4);
        }
        const uint32_t b_s = sb + B_OFF + (uint32_t)((kc & 3) * B_STAGE);

        // double-buffered fragments: load ks into buf[ks&1], prefetch ks+1
        uint32_t af[2][2][4], bf[2][2][4];
        auto ldsm_ks = [&](int ks, int buf) {
            uint32_t kbase = (uint32_t)(ks * 32) + kh16;
#pragma unroll
            for (int mt = 0; mt < 2; mt++)
                ldm_x4(abase[mt] + (kbase ^ apat[mt]),
                       af[buf][mt][0], af[buf][mt][1], af[buf][mt][2], af[buf][mt][3]);
#pragma unroll
            for (int bt = 0; bt < 2; bt++) {
                uint32_t off = (uint32_t)((wn * 32 + bt * 16 + lrow) * 128 +
                                          ks * 32 + lcol);
                ldm_x4(b_s + sw128(off),
                       bf[buf][bt][0], bf[buf][bt][1], bf[buf][bt][2], bf[buf][bt][3]);
            }
        };

        ldsm_ks(0, 0);
#pragma unroll
        for (int ks = 0; ks < 4; ks++) {
            const int cur = ks & 1;
            if (ks < 3) ldsm_ks(ks + 1, cur ^ 1);    // prefetch before MMAs
#pragma unroll
            for (int mt = 0; mt < 2; mt++)
#pragma unroll
                for (int nt = 0; nt < 4; nt++)
                    mma16816(acc[mt][nt], af[cur][mt],
                             bf[cur][nt >> 1][nt & 1], bf[cur][nt >> 1][(nt & 1) + 2]);
        }
    }

    // ---- epilogue: 4 groups of 32 instances; transpose in smem (reuse slab) ----
    float* fs = reinterpret_cast<float*>(sm);        // [64][33] floats = 8448 B
#pragma unroll 1
    for (int g = 0; g < 4; g++) {
        __syncthreads();
        if (wn == g) {
#pragma unroll
            for (int mt = 0; mt < 2; mt++)
#pragma unroll
                for (int nt = 0; nt < 4; nt++)
#pragma unroll
                    for (int e = 0; e < 4; e++) {
                        int row = (l >> 2) + ((e >> 1) << 3);
                        int col = ((l & 3) << 1) + (e & 1);
                        int ml  = wm * 32 + mt * 16 + row;   // 0..63
                        int nl  = (nt << 3) + col;           // 0..31
                        fs[ml * 33 + nl] = __logf(acc[mt][nt][e]) - LOG_K;
                    }
        }
        __syncthreads();
        const int i_loc = tid >> 3;                  // 0..31
        const int mc    = (tid & 7) << 3;            // 0..56
        float* ob = out + ((size_t)b << 18)
                        + (((size_t)(n0 + g * 32 + i_loc)) << 10) + p * 64 + mc;
#pragma unroll
        for (int j = 0; j < 2; j++) {
            float4 v;
            v.x = fs[(mc + j * 4 + 0) * 33 + i_loc];
            v.y = fs[(mc + j * 4 + 1) * 33 + i_loc];
            v.z = fs[(mc + j * 4 + 2) * 33 + i_loc];
            v.w = fs[(mc + j * 4 + 3) * 33 + i_loc];
            *reinterpret_cast<float4*>(ob + j * 4) = v;
        }
    }
}

// ---------------------------------------------------------------------------
extern "C" void kernel_launch(void* const* d_in, const int* in_sizes, int n_in,
                              void* d_out, int out_size) {
    const float* x    = (const float*)d_in[0];
    const float* offs = (const float*)d_in[1];
    if (n_in >= 2 && in_sizes[0] == NI * KTOT) {  // defensive: swap if order flipped
        const float* t = x; x = offs; offs = t;
    }
    float* out = (float*)d_out;

    __half* Bp = nullptr;
    cudaGetSymbolAddress((void**)&Bp, g_B);
    cudaFuncSetAttribute(mex_fused, cudaFuncAttributeMaxDynamicSharedMemorySize,
                         SMEM_BYTES);

    mex_pass0<<<(NI * KTOT + 255) / 256, 256>>>(offs, Bp);
    dim3 grid(2, 64 * 16);
    mex_fused<<<grid, 256, SMEM_BYTES>>>(x, Bp, out);
}